// round 1
// baseline (speedup 1.0000x reference)
#include <cuda_runtime.h>
#include <cuda_bf16.h>
#include <cstdint>

// Problem dims (fixed by reference)
#define Bb 8
#define Cc 512
#define Tt 4
#define NN 256
#define LL 1024   // Tt*NN
#define HH 8
#define DD 64

// Scratch (device globals; allocation-free contract)
__device__ float g_s0[Bb * Cc * LL];                     // 16 MB  spikes after proj BN+LIF (0/1)
__device__ float g_y[3 * Bb * Cc * LL];                  // 48 MB  qkv pre-activation
__device__ float g_qkv[3 * Bb * HH * LL * DD];           // 48 MB  q,k,v spikes in (w,b,h,l,d)
__device__ unsigned long long g_bits[2 * Bb * HH * LL];  // 1 MB   q,k packed along d (64 bits)
__device__ float g_sattn[Bb * Cc * LL];                  // 16 MB  attention spikes (0/1)

// ---------------------------------------------------------------------------
// Kernel 1: proj BN + multi-step LIF  ->  g_s0 (B,C,L), l = t*NN + n
// ---------------------------------------------------------------------------
__global__ void k_bn_lif_proj(const float* __restrict__ x,
                              const float* __restrict__ gp,
                              const float* __restrict__ bpn,
                              const float* __restrict__ mp,
                              const float* __restrict__ vp) {
    int idx = blockIdx.x * blockDim.x + threadIdx.x;  // over B*C*NN
    if (idx >= Bb * Cc * NN) return;
    int n = idx % NN;
    int c = (idx / NN) % Cc;
    int b = idx / (NN * Cc);

    float sc = gp[c] / sqrtf(vp[c] + 1e-5f);
    float sh = bpn[c] - mp[c] * sc;

    const float* xp = x + ((size_t)(b * Cc + c) * Tt) * NN + n;
    float* sp = g_s0 + (size_t)(b * Cc + c) * LL + n;

    float v = 0.0f;
#pragma unroll
    for (int t = 0; t < Tt; t++) {
        float xb = xp[(size_t)t * NN] * sc + sh;
        v = v + (xb - v) / 1.5f;
        float s = (v >= 1.0f) ? 1.0f : 0.0f;
        sp[(size_t)t * NN] = s;
        if (s != 0.0f) v = 0.0f;
    }
}

// ---------------------------------------------------------------------------
// Kernel 2: QKV projection GEMM.  Y[w,b,o,l] = sum_c W_w[o,c] * s0[b,c,l]
// 64x64 tile, BK=16, 4x4 per thread, 256 threads.
// grid = (LL/64, Cc/64, 3*Bb)
// ---------------------------------------------------------------------------
__global__ void k_gemm_qkv(const float* __restrict__ wq,
                           const float* __restrict__ wk,
                           const float* __restrict__ wv) {
    int w = blockIdx.z / Bb;
    int b = blockIdx.z % Bb;
    const float* Wm = (w == 0) ? wq : (w == 1) ? wk : wv;
    const float* Xb = g_s0 + (size_t)b * Cc * LL;
    float* Yb = g_y + (size_t)(w * Bb + b) * Cc * LL;

    int l0 = blockIdx.x * 64;
    int o0 = blockIdx.y * 64;
    int tid = threadIdx.x;
    int tx = tid & 15, ty = tid >> 4;

    __shared__ float As[16][64];  // [kk][om]
    __shared__ float Bs[16][64];  // [kk][ln]

    float acc[4][4] = {};

    for (int k0 = 0; k0 < Cc; k0 += 16) {
        {
            int om = tid >> 2, kk = (tid & 3) * 4;
            float4 a4 = *(const float4*)(Wm + (size_t)(o0 + om) * Cc + k0 + kk);
            As[kk + 0][om] = a4.x;
            As[kk + 1][om] = a4.y;
            As[kk + 2][om] = a4.z;
            As[kk + 3][om] = a4.w;
        }
        {
            int kk = tid >> 4, ln = (tid & 15) * 4;
            float4 b4 = *(const float4*)(Xb + (size_t)(k0 + kk) * LL + l0 + ln);
            *(float4*)&Bs[kk][ln] = b4;
        }
        __syncthreads();
#pragma unroll
        for (int kk = 0; kk < 16; kk++) {
            float a[4], bv[4];
#pragma unroll
            for (int i = 0; i < 4; i++) a[i] = As[kk][ty * 4 + i];
#pragma unroll
            for (int j = 0; j < 4; j++) bv[j] = Bs[kk][tx * 4 + j];
#pragma unroll
            for (int i = 0; i < 4; i++)
#pragma unroll
                for (int j = 0; j < 4; j++) acc[i][j] += a[i] * bv[j];
        }
        __syncthreads();
    }
#pragma unroll
    for (int i = 0; i < 4; i++) {
        int o = o0 + ty * 4 + i;
        float4 r = make_float4(acc[i][0], acc[i][1], acc[i][2], acc[i][3]);
        *(float4*)&Yb[(size_t)o * LL + l0 + tx * 4] = r;
    }
}

// ---------------------------------------------------------------------------
// Kernel 3: per-branch BN + LIF -> spikes in (w,b,h,l,d) layout (float 0/1)
// ---------------------------------------------------------------------------
__global__ void k_bn_lif_qkv(const float* __restrict__ gq, const float* __restrict__ bq,
                             const float* __restrict__ mq, const float* __restrict__ vq,
                             const float* __restrict__ gk, const float* __restrict__ bk,
                             const float* __restrict__ mk, const float* __restrict__ vk,
                             const float* __restrict__ gv, const float* __restrict__ bv,
                             const float* __restrict__ mv, const float* __restrict__ vv) {
    int idx = blockIdx.x * blockDim.x + threadIdx.x;  // over 3*B*C*NN
    if (idx >= 3 * Bb * Cc * NN) return;
    int n = idx % NN;
    int o = (idx / NN) % Cc;
    int b = (idx / (NN * Cc)) % Bb;
    int w = idx / (NN * Cc * Bb);

    const float *gg, *bb, *mm, *vvv;
    if (w == 0) { gg = gq; bb = bq; mm = mq; vvv = vq; }
    else if (w == 1) { gg = gk; bb = bk; mm = mk; vvv = vk; }
    else { gg = gv; bb = bv; mm = mv; vvv = vv; }

    float sc = gg[o] / sqrtf(vvv[o] + 1e-5f);
    float sh = bb[o] - mm[o] * sc;

    const float* yp = g_y + (size_t)((w * Bb + b) * Cc + o) * LL + n;
    int h = o >> 6, dd = o & 63;
    float* qp = g_qkv + ((size_t)((w * Bb + b) * HH + h) * LL) * DD + (size_t)n * DD + dd;

    float v = 0.0f;
#pragma unroll
    for (int t = 0; t < Tt; t++) {
        float yb = yp[(size_t)t * NN] * sc + sh;
        v = v + (yb - v) / 1.5f;
        float s = (v >= 1.0f) ? 1.0f : 0.0f;
        qp[(size_t)t * NN * DD] = s;
        if (s != 0.0f) v = 0.0f;
    }
}

// ---------------------------------------------------------------------------
// Kernel 3b: pack q,k spikes into 64-bit masks along d. One warp -> 32 rows.
// ---------------------------------------------------------------------------
__global__ void k_pack_bits() {
    int warp = (blockIdx.x * blockDim.x + threadIdx.x) >> 5;
    int lane = threadIdx.x & 31;
    int row0 = warp * 32;  // row r = ((w*B+b)*H+h)*L + l, w in {0,1}
    if (row0 >= 2 * Bb * HH * LL) return;
    const float* base = g_qkv;
#pragma unroll 4
    for (int rr = 0; rr < 32; rr++) {
        int r = row0 + rr;
        float v0 = base[(size_t)r * DD + lane];
        float v1 = base[(size_t)r * DD + 32 + lane];
        unsigned m0 = __ballot_sync(0xffffffffu, v0 > 0.5f);
        unsigned m1 = __ballot_sync(0xffffffffu, v1 > 0.5f);
        if (lane == 0)
            g_bits[r] = (unsigned long long)m0 | ((unsigned long long)m1 << 32);
    }
}

// ---------------------------------------------------------------------------
// Kernel 4: attention. S = popc(q&k); O = S @ V * 0.125; spike(O/1.5 - 1).
// CTA: (b,h) x 64-row l tile, full d=64 output. grid = (LL/64, Bb*HH)
// ---------------------------------------------------------------------------
__global__ void k_attn() {
    int l0 = blockIdx.x * 64;
    int bh = blockIdx.y;
    int b = bh >> 3, h = bh & 7;

    const unsigned long long* qb = g_bits + ((size_t)(0 * Bb + b) * HH + h) * LL;
    const unsigned long long* kb = g_bits + ((size_t)(1 * Bb + b) * HH + h) * LL;
    const float* V = g_qkv + ((size_t)((2 * Bb + b) * HH + h) * LL) * DD;

    __shared__ unsigned long long Qs[64], Ks[64];
    __shared__ float Ss[64][65];
    __shared__ float Vs[64][64];

    int tid = threadIdx.x;
    int tx = tid & 15, ty = tid >> 4;

    if (tid < 64) Qs[tid] = qb[l0 + tid];

    float acc[4][4] = {};

    for (int k0 = 0; k0 < LL; k0 += 64) {
        if (tid < 64) Ks[tid] = kb[k0 + tid];
#pragma unroll
        for (int j = 0; j < 4; j++) {
            int id = tid * 4 + j;  // 1024 float4 loads
            int kk = id >> 4, dd4 = (id & 15) * 4;
            *(float4*)&Vs[kk][dd4] = *(const float4*)&V[(size_t)(k0 + kk) * DD + dd4];
        }
        __syncthreads();
        // Stage 1: S tile via popcount (exact QK^T over binary d=64)
#pragma unroll
        for (int i = 0; i < 4; i++) {
            unsigned long long q = Qs[ty * 4 + i];
#pragma unroll
            for (int j = 0; j < 4; j++)
                Ss[ty * 4 + i][tx * 4 + j] = (float)__popcll(q & Ks[tx * 4 + j]);
        }
        __syncthreads();
        // Stage 2: O += S @ V
#pragma unroll
        for (int k = 0; k < 64; k++) {
            float a[4], bv[4];
#pragma unroll
            for (int i = 0; i < 4; i++) a[i] = Ss[ty * 4 + i][k];
#pragma unroll
            for (int j = 0; j < 4; j++) bv[j] = Vs[k][tx * 4 + j];
#pragma unroll
            for (int i = 0; i < 4; i++)
#pragma unroll
                for (int j = 0; j < 4; j++) acc[i][j] += a[i] * bv[j];
        }
        __syncthreads();
    }

#pragma unroll
    for (int i = 0; i < 4; i++) {
        int l = l0 + ty * 4 + i;
#pragma unroll
        for (int j = 0; j < 4; j++) {
            int dd = tx * 4 + j;
            float o = acc[i][j] * 0.125f;
            float s = ((o / 1.5f - 1.0f) >= 0.0f) ? 1.0f : 0.0f;
            g_sattn[((size_t)b * Cc + h * 64 + dd) * LL + l] = s;
        }
    }
}

// ---------------------------------------------------------------------------
// Kernel 5: output projection. out[b,o,l] = bp[o] + sum_c wp[o,c]*sattn[b,c,l]
// grid = (LL/64, Cc/64, Bb)
// ---------------------------------------------------------------------------
__global__ void k_gemm_out(const float* __restrict__ wp,
                           const float* __restrict__ bp,
                           float* __restrict__ out) {
    int b = blockIdx.z;
    const float* Xb = g_sattn + (size_t)b * Cc * LL;
    float* Yb = out + (size_t)b * Cc * LL;

    int l0 = blockIdx.x * 64;
    int o0 = blockIdx.y * 64;
    int tid = threadIdx.x;
    int tx = tid & 15, ty = tid >> 4;

    __shared__ float As[16][64];
    __shared__ float Bs[16][64];

    float acc[4][4] = {};

    for (int k0 = 0; k0 < Cc; k0 += 16) {
        {
            int om = tid >> 2, kk = (tid & 3) * 4;
            float4 a4 = *(const float4*)(wp + (size_t)(o0 + om) * Cc + k0 + kk);
            As[kk + 0][om] = a4.x;
            As[kk + 1][om] = a4.y;
            As[kk + 2][om] = a4.z;
            As[kk + 3][om] = a4.w;
        }
        {
            int kk = tid >> 4, ln = (tid & 15) * 4;
            float4 b4 = *(const float4*)(Xb + (size_t)(k0 + kk) * LL + l0 + ln);
            *(float4*)&Bs[kk][ln] = b4;
        }
        __syncthreads();
#pragma unroll
        for (int kk = 0; kk < 16; kk++) {
            float a[4], bv[4];
#pragma unroll
            for (int i = 0; i < 4; i++) a[i] = As[kk][ty * 4 + i];
#pragma unroll
            for (int j = 0; j < 4; j++) bv[j] = Bs[kk][tx * 4 + j];
#pragma unroll
            for (int i = 0; i < 4; i++)
#pragma unroll
                for (int j = 0; j < 4; j++) acc[i][j] += a[i] * bv[j];
        }
        __syncthreads();
    }
#pragma unroll
    for (int i = 0; i < 4; i++) {
        int o = o0 + ty * 4 + i;
        float bi = bp[o];
        float4 r = make_float4(acc[i][0] + bi, acc[i][1] + bi, acc[i][2] + bi, acc[i][3] + bi);
        *(float4*)&Yb[(size_t)o * LL + l0 + tx * 4] = r;
    }
}

// ---------------------------------------------------------------------------
extern "C" void kernel_launch(void* const* d_in, const int* in_sizes, int n_in,
                              void* d_out, int out_size) {
    const float* x   = (const float*)d_in[0];
    const float* wq  = (const float*)d_in[1];
    const float* wk  = (const float*)d_in[2];
    const float* wv  = (const float*)d_in[3];
    const float* wp  = (const float*)d_in[4];
    const float* bp  = (const float*)d_in[5];
    const float* gq  = (const float*)d_in[6];
    const float* bq  = (const float*)d_in[7];
    const float* mq  = (const float*)d_in[8];
    const float* vq  = (const float*)d_in[9];
    const float* gk  = (const float*)d_in[10];
    const float* bk  = (const float*)d_in[11];
    const float* mk  = (const float*)d_in[12];
    const float* vk  = (const float*)d_in[13];
    const float* gv  = (const float*)d_in[14];
    const float* bv  = (const float*)d_in[15];
    const float* mv  = (const float*)d_in[16];
    const float* vv  = (const float*)d_in[17];
    const float* gp  = (const float*)d_in[18];
    const float* bpn = (const float*)d_in[19];
    const float* mp  = (const float*)d_in[20];
    const float* vp  = (const float*)d_in[21];
    float* out = (float*)d_out;

    k_bn_lif_proj<<<(Bb * Cc * NN + 255) / 256, 256>>>(x, gp, bpn, mp, vp);
    k_gemm_qkv<<<dim3(LL / 64, Cc / 64, 3 * Bb), 256>>>(wq, wk, wv);
    k_bn_lif_qkv<<<(3 * Bb * Cc * NN + 255) / 256, 256>>>(gq, bq, mq, vq,
                                                          gk, bk, mk, vk,
                                                          gv, bv, mv, vv);
    k_pack_bits<<<(2 * Bb * HH * LL / 32 + 7) / 8, 256>>>();
    k_attn<<<dim3(LL / 64, Bb * HH), 256>>>();
    k_gemm_out<<<dim3(LL / 64, Cc / 64, Bb), 256>>>(wp, bp, out);
}

// round 5
// speedup vs baseline: 1.6962x; 1.6962x over previous
#include <cuda_runtime.h>
#include <cuda_bf16.h>
#include <cstdint>

#define Bb 8
#define Cc 512
#define Tt 4
#define NN 256
#define LL 1024
#define HH 8
#define DD 64

typedef __nv_bfloat16 bf16;

// Scratch
__device__ bf16  g_wsp[3 * Cc * Cc];       // wp exact 3-way bf16 split
__device__ bf16  g_s0b[Bb * Cc * LL];      // proj spikes bf16 [b][c][l]
__device__ float g_y[3 * Bb * Cc * LL];    // qkv pre-activation fp32
__device__ bf16  g_qb[Bb * HH * LL * DD];  // q spikes [b][h][l][d]
__device__ bf16  g_kb[Bb * Cc * LL];       // k spikes [b][c][l] (= [b][h][d][l])
__device__ bf16  g_vb[Bb * HH * LL * DD];  // v spikes [b][h][l][d]
__device__ bf16  g_sattnb[Bb * Cc * LL];   // attn spikes [b][c][l]

// ---------------------------------------------------------------------------
__device__ __forceinline__ uint32_t smem_u32(const void* p) {
    return (uint32_t)__cvta_generic_to_shared(p);
}
__device__ __forceinline__ void ldsm4(uint32_t* r, uint32_t a) {
    asm volatile("ldmatrix.sync.aligned.m8n8.x4.shared.b16 {%0,%1,%2,%3}, [%4];"
                 : "=r"(r[0]), "=r"(r[1]), "=r"(r[2]), "=r"(r[3]) : "r"(a));
}
__device__ __forceinline__ void ldsm4t(uint32_t* r, uint32_t a) {
    asm volatile("ldmatrix.sync.aligned.m8n8.x4.trans.shared.b16 {%0,%1,%2,%3}, [%4];"
                 : "=r"(r[0]), "=r"(r[1]), "=r"(r[2]), "=r"(r[3]) : "r"(a));
}
__device__ __forceinline__ void mma16816(float* c, const uint32_t* a, uint32_t b0, uint32_t b1) {
    asm volatile(
        "mma.sync.aligned.m16n8k16.row.col.f32.bf16.bf16.f32 "
        "{%0,%1,%2,%3}, {%4,%5,%6,%7}, {%8,%9}, {%0,%1,%2,%3};"
        : "+f"(c[0]), "+f"(c[1]), "+f"(c[2]), "+f"(c[3])
        : "r"(a[0]), "r"(a[1]), "r"(a[2]), "r"(a[3]), "r"(b0), "r"(b1));
}
__device__ __forceinline__ uint32_t packbf(float lo, float hi) {
    uint32_t l = (uint32_t)__bfloat16_as_ushort(__float2bfloat16(lo));
    uint32_t h = (uint32_t)__bfloat16_as_ushort(__float2bfloat16(hi));
    return l | (h << 16);
}

// ---------------------------------------------------------------------------
// Kernel 0: exact 3-way bf16 split of wp only.
// ---------------------------------------------------------------------------
__global__ void k_split_w(const float* __restrict__ wp) {
    int idx = blockIdx.x * blockDim.x + threadIdx.x;
    if (idx >= Cc * Cc) return;
    float w = wp[idx];
    bf16 hi = __float2bfloat16(w);
    float r1 = w - __bfloat162float(hi);
    bf16 mid = __float2bfloat16(r1);
    float r2 = r1 - __bfloat162float(mid);
    g_wsp[0 * Cc * Cc + idx] = hi;
    g_wsp[1 * Cc * Cc + idx] = mid;
    g_wsp[2 * Cc * Cc + idx] = __float2bfloat16(r2);
}

// ---------------------------------------------------------------------------
// Kernel 1: proj BN + multi-step LIF -> g_s0b
// ---------------------------------------------------------------------------
__global__ void k_bn_lif_proj(const float* __restrict__ x,
                              const float* __restrict__ gp,
                              const float* __restrict__ bpn,
                              const float* __restrict__ mp,
                              const float* __restrict__ vp) {
    int idx = blockIdx.x * blockDim.x + threadIdx.x;
    if (idx >= Bb * Cc * NN) return;
    int n = idx % NN;
    int c = (idx / NN) % Cc;
    int b = idx / (NN * Cc);

    float sc = gp[c] / sqrtf(vp[c] + 1e-5f);
    float sh = bpn[c] - mp[c] * sc;

    const float* xp = x + ((size_t)(b * Cc + c) * Tt) * NN + n;
    bf16* sp = g_s0b + (size_t)(b * Cc + c) * LL + n;

    float v = 0.0f;
#pragma unroll
    for (int t = 0; t < Tt; t++) {
        float xb = xp[(size_t)t * NN] * sc + sh;
        v = v + (xb - v) / 1.5f;
        float s = (v >= 1.0f) ? 1.0f : 0.0f;
        sp[(size_t)t * NN] = __float2bfloat16(s);
        if (s != 0.0f) v = 0.0f;
    }
}

// ---------------------------------------------------------------------------
// Kernel 2: QKV projection, BITWISE fp32 FFMA (ascending k, single acc).
// 128x128 tile, BK=16, 256 threads, 8x8/thread, double-buffered smem.
// grid = (LL/128, Cc/128, 3*Bb)
// ---------------------------------------------------------------------------
__global__ __launch_bounds__(256, 2) void k_gemm_qkv_f32(const float* __restrict__ wq,
                                                         const float* __restrict__ wk,
                                                         const float* __restrict__ wv) {
    int z = blockIdx.z;
    int w = z >> 3, b = z & 7;
    const float* A = (w == 0) ? wq : (w == 1) ? wk : wv;
    const bf16* B = g_s0b + (size_t)b * Cc * LL;
    float* C = g_y + (size_t)z * Cc * LL;

    int o0 = blockIdx.y * 128, l0 = blockIdx.x * 128;
    int tid = threadIdx.x;
    int tx = tid & 15, ty = tid >> 4;

    __shared__ float As[2][16][128];
    __shared__ float Bs[2][16][128];

    int aRow = tid >> 1, aK = (tid & 1) * 8;
    int bRow = tid >> 4, bCh = tid & 15;

    float acc[8][8];
#pragma unroll
    for (int i = 0; i < 8; i++)
#pragma unroll
        for (int j = 0; j < 8; j++) acc[i][j] = 0.0f;

    float4 pa0, pa1;
    uint4 pbv;

#define PREF(k0)                                                              \
    {                                                                         \
        pa0 = *(const float4*)(A + (size_t)(o0 + aRow) * Cc + (k0) + aK);     \
        pa1 = *(const float4*)(A + (size_t)(o0 + aRow) * Cc + (k0) + aK + 4); \
        pbv = *(const uint4*)(B + (size_t)((k0) + bRow) * LL + l0 + bCh * 8); \
    }
#define STORE(buf)                                                              \
    {                                                                           \
        As[buf][aK + 0][aRow] = pa0.x; As[buf][aK + 1][aRow] = pa0.y;           \
        As[buf][aK + 2][aRow] = pa0.z; As[buf][aK + 3][aRow] = pa0.w;           \
        As[buf][aK + 4][aRow] = pa1.x; As[buf][aK + 5][aRow] = pa1.y;           \
        As[buf][aK + 6][aRow] = pa1.z; As[buf][aK + 7][aRow] = pa1.w;           \
        const __nv_bfloat162* pb2 = (const __nv_bfloat162*)&pbv;                \
        float4 f0, f1;                                                          \
        { float2 t0 = __bfloat1622float2(pb2[0]); f0.x = t0.x; f0.y = t0.y; }   \
        { float2 t1 = __bfloat1622float2(pb2[1]); f0.z = t1.x; f0.w = t1.y; }   \
        { float2 t2 = __bfloat1622float2(pb2[2]); f1.x = t2.x; f1.y = t2.y; }   \
        { float2 t3 = __bfloat1622float2(pb2[3]); f1.z = t3.x; f1.w = t3.y; }   \
        *(float4*)&Bs[buf][bRow][bCh * 8] = f0;                                 \
        *(float4*)&Bs[buf][bRow][bCh * 8 + 4] = f1;                             \
    }

    PREF(0);
    STORE(0);
    __syncthreads();

    for (int kt = 0; kt < 32; kt++) {
        int cur = kt & 1;
        if (kt < 31) PREF((kt + 1) * 16);
#pragma unroll
        for (int kk = 0; kk < 16; kk++) {
            float a[8], bv[8];
            *(float4*)&a[0]  = *(const float4*)&As[cur][kk][ty * 8];
            *(float4*)&a[4]  = *(const float4*)&As[cur][kk][ty * 8 + 4];
            *(float4*)&bv[0] = *(const float4*)&Bs[cur][kk][tx * 8];
            *(float4*)&bv[4] = *(const float4*)&Bs[cur][kk][tx * 8 + 4];
#pragma unroll
            for (int i = 0; i < 8; i++)
#pragma unroll
                for (int j = 0; j < 8; j++) acc[i][j] += a[i] * bv[j];
        }
        if (kt < 31) { STORE(!cur); }
        __syncthreads();
    }
#undef PREF
#undef STORE

#pragma unroll
    for (int i = 0; i < 8; i++) {
        int o = o0 + ty * 8 + i;
        *(float4*)&C[(size_t)o * LL + l0 + tx * 8]     = *(float4*)&acc[i][0];
        *(float4*)&C[(size_t)o * LL + l0 + tx * 8 + 4] = *(float4*)&acc[i][4];
    }
}

// ---------------------------------------------------------------------------
// Kernel 3: per-branch BN + LIF -> q:[b][h][l][d]  k:[b][c][l]  v:[b][h][l][d]
// ---------------------------------------------------------------------------
__global__ void k_bn_lif_qkv(const float* __restrict__ gq, const float* __restrict__ bq,
                             const float* __restrict__ mq, const float* __restrict__ vq,
                             const float* __restrict__ gk, const float* __restrict__ bk,
                             const float* __restrict__ mk, const float* __restrict__ vk,
                             const float* __restrict__ gv, const float* __restrict__ bv,
                             const float* __restrict__ mv, const float* __restrict__ vv) {
    int idx = blockIdx.x * blockDim.x + threadIdx.x;
    if (idx >= 3 * Bb * Cc * NN) return;
    int n = idx % NN;
    int o = (idx / NN) % Cc;
    int b = (idx / (NN * Cc)) % Bb;
    int w = idx / (NN * Cc * Bb);

    const float *gg, *bb, *mm, *vvv;
    if (w == 0) { gg = gq; bb = bq; mm = mq; vvv = vq; }
    else if (w == 1) { gg = gk; bb = bk; mm = mk; vvv = vk; }
    else { gg = gv; bb = bv; mm = mv; vvv = vv; }

    float sc = gg[o] / sqrtf(vvv[o] + 1e-5f);
    float sh = bb[o] - mm[o] * sc;

    const float* yp = g_y + (size_t)((w * Bb + b) * Cc + o) * LL + n;
    int h = o >> 6, dd = o & 63;

    bf16* outp;
    size_t stride;
    if (w == 1) {  // k: [b][c][l]
        outp = g_kb + (size_t)(b * Cc + o) * LL + n;
        stride = NN;
    } else {       // q,v: [b][h][l][d]
        bf16* base = (w == 0) ? g_qb : g_vb;
        outp = base + ((size_t)(b * HH + h) * LL + n) * DD + dd;
        stride = (size_t)NN * DD;
    }

    float v = 0.0f;
#pragma unroll
    for (int t = 0; t < Tt; t++) {
        float yb = yp[(size_t)t * NN] * sc + sh;
        v = v + (yb - v) / 1.5f;
        float s = (v >= 1.0f) ? 1.0f : 0.0f;
        outp[(size_t)t * stride] = __float2bfloat16(s);
        if (s != 0.0f) v = 0.0f;
    }
}

// ---------------------------------------------------------------------------
// Kernel 4: attention on tensor cores (exact: binary inputs, integer sums).
// CTA = (b,h) x 128 q-rows. 8 warps, each 16 q-rows x full d=64 output.
// S fragments repacked as A fragments (no smem round-trip).
// grid = (LL/128, Bb*HH)
// ---------------------------------------------------------------------------
__global__ __launch_bounds__(256) void k_attn_mma() {
    int l0 = blockIdx.x * 128;
    int bh = blockIdx.y;
    int b = bh >> 3, h = bh & 7;

    const bf16* Q = g_qb + (size_t)bh * LL * DD;              // [l][d]
    const bf16* K = g_kb + (size_t)(b * Cc + h * 64) * LL;    // [d][l]
    const bf16* V = g_vb + (size_t)bh * LL * DD;              // [l][d]

    __shared__ bf16 Qs[128 * 72];   // rows of 72 bf16 (144B) for conflict-free ldsm
    __shared__ bf16 Ks[64 * 64];    // [d][key], 16B-chunk xor swizzle
    __shared__ bf16 Vs[64 * 64];    // [key][d], 16B-chunk xor swizzle

    int tid = threadIdx.x, lane = tid & 31, warp = tid >> 5;
    const uint32_t sQ = smem_u32(Qs), sK = smem_u32(Ks), sV = smem_u32(Vs);

    // load Q tile: 128 rows x 8 chunks of 16B (FIXED: full d=64 per row)
#pragma unroll
    for (int t = 0; t < 4; t++) {
        int id = tid + t * 256;
        int r = id >> 3, c = id & 7;
        uint4 qv = *(const uint4*)(Q + (size_t)(l0 + r) * DD + c * 8);
        *(uint4*)((char*)Qs + r * 144 + c * 16) = qv;
    }
    __syncthreads();

    // Q fragments (persistent): m16 x k64 per warp
    uint32_t aq[4][4];
    {
        int row = warp * 16 + (lane & 15);
#pragma unroll
        for (int kc = 0; kc < 4; kc++)
            ldsm4(aq[kc], sQ + row * 144 + kc * 32 + (lane >> 4) * 16);
    }

    float oacc[8][4];
#pragma unroll
    for (int i = 0; i < 8; i++)
#pragma unroll
        for (int j = 0; j < 4; j++) oacc[i][j] = 0.0f;

    for (int k0 = 0; k0 < LL; k0 += 64) {
        __syncthreads();
        // load K tile [d=64][key 64] and V tile [key=64][d 64], swizzled
#pragma unroll
        for (int t = 0; t < 2; t++) {
            int id = tid + t * 256;
            int r = id >> 3, c = id & 7;
            int x = c ^ (r & 7);
            uint4 kv = *(const uint4*)(K + (size_t)r * LL + k0 + c * 8);
            *(uint4*)((char*)Ks + r * 128 + x * 16) = kv;
            uint4 vv = *(const uint4*)(V + (size_t)(k0 + r) * DD + c * 8);
            *(uint4*)((char*)Vs + r * 128 + x * 16) = vv;
        }
        __syncthreads();

        // Stage 1: S(m16 x n64) = Q @ K^T   (k-dim = d = 64)
        float sacc[8][4];
#pragma unroll
        for (int i = 0; i < 8; i++)
#pragma unroll
            for (int j = 0; j < 4; j++) sacc[i][j] = 0.0f;
#pragma unroll
        for (int nb = 0; nb < 4; nb++) {
#pragma unroll
            for (int ks = 0; ks < 4; ks++) {
                uint32_t bf[4];
                int krow = ks * 16 + (lane & 7) + ((lane >> 3) & 1) * 8;
                int ch = nb * 2 + (lane >> 4);
                int x = ch ^ (krow & 7);
                ldsm4t(bf, sK + krow * 128 + x * 16);
                mma16816(sacc[nb * 2],     aq[ks], bf[0], bf[1]);
                mma16816(sacc[nb * 2 + 1], aq[ks], bf[2], bf[3]);
            }
        }
        // Repack S C-fragments as A-fragments (exact: S integer <= 64)
        uint32_t sa[4][4];
#pragma unroll
        for (int kb = 0; kb < 4; kb++) {
            sa[kb][0] = packbf(sacc[2 * kb][0],     sacc[2 * kb][1]);
            sa[kb][1] = packbf(sacc[2 * kb][2],     sacc[2 * kb][3]);
            sa[kb][2] = packbf(sacc[2 * kb + 1][0], sacc[2 * kb + 1][1]);
            sa[kb][3] = packbf(sacc[2 * kb + 1][2], sacc[2 * kb + 1][3]);
        }
        // Stage 2: O(m16 x n64) += S @ V    (k-dim = key = 64)
#pragma unroll
        for (int nb = 0; nb < 4; nb++) {
#pragma unroll
            for (int kb = 0; kb < 4; kb++) {
                uint32_t bf[4];
                int krow = kb * 16 + (lane & 7) + ((lane >> 3) & 1) * 8;
                int ch = nb * 2 + (lane >> 4);
                int x = ch ^ (krow & 7);
                ldsm4t(bf, sV + krow * 128 + x * 16);
                mma16816(oacc[nb * 2],     sa[kb], bf[0], bf[1]);
                mma16816(oacc[nb * 2 + 1], sa[kb], bf[2], bf[3]);
            }
        }
    }

    // epilogue: scale, spike, store to [b][c=h*64+d][l]
    int row = warp * 16 + (lane >> 2);
#pragma unroll
    for (int nj = 0; nj < 8; nj++) {
        int col = nj * 8 + (lane & 3) * 2;
#pragma unroll
        for (int e = 0; e < 4; e++) {
            int r = row + (e >> 1) * 8;
            int c = col + (e & 1);
            float o = oacc[nj][e] * 0.125f;
            float s = ((o / 1.5f - 1.0f) >= 0.0f) ? 1.0f : 0.0f;
            g_sattnb[((size_t)b * Cc + h * 64 + c) * LL + (l0 + r)] = __float2bfloat16(s);
        }
    }
}

// ---------------------------------------------------------------------------
// Kernel 5: output projection via 3-split bf16 MMA (after last threshold).
// CTA tile 128x128, BK=32 over K'=1536, 8 warps.
// ---------------------------------------------------------------------------
__global__ __launch_bounds__(256, 2) void k_gemm_out_mma(const float* __restrict__ bp,
                                                         float* __restrict__ out) {
    const bf16* A = g_wsp;                                 // [3][512][512]
    const bf16* B = g_sattnb + (size_t)blockIdx.z * Cc * LL;
    float* C = out + (size_t)blockIdx.z * Cc * LL;

    __shared__ bf16 As[128 * 40];
    __shared__ bf16 Bs[32 * 128];

    const int tid = threadIdx.x;
    const int lane = tid & 31, warp = tid >> 5;
    const int wm = warp >> 1, wn = warp & 1;
    const int o0 = blockIdx.y * 128, l0 = blockIdx.x * 128;

    float acc[2][8][4];
#pragma unroll
    for (int i = 0; i < 2; i++)
#pragma unroll
        for (int j = 0; j < 8; j++)
#pragma unroll
            for (int k = 0; k < 4; k++) acc[i][j][k] = 0.0f;

    int aM[2], aK[2], bK[2], bX[2];
#pragma unroll
    for (int t = 0; t < 2; t++) {
        int id = tid + t * 256;
        aM[t] = id >> 2; aK[t] = id & 3;
        bK[t] = id >> 4; bX[t] = id & 15;
    }
    uint4 pa[2], pb[2];
    const uint32_t sA = smem_u32(As), sB = smem_u32(Bs);

#define LOADG(kk)                                                                      \
    {                                                                                  \
        int split = ((kk) * 32) >> 9;                                                  \
        int c0 = ((kk) * 32) & 511;                                                    \
        const bf16* Ab = A + (size_t)split * (Cc * Cc);                                \
        _Pragma("unroll") for (int t = 0; t < 2; t++)                                  \
            pa[t] = *(const uint4*)(Ab + (size_t)(o0 + aM[t]) * Cc + c0 + aK[t] * 8);  \
        _Pragma("unroll") for (int t = 0; t < 2; t++)                                  \
            pb[t] = *(const uint4*)(B + (size_t)(c0 + bK[t]) * LL + l0 + bX[t] * 8);   \
    }
#define STOS()                                                                         \
    {                                                                                  \
        _Pragma("unroll") for (int t = 0; t < 2; t++)                                  \
            *(uint4*)((char*)As + aM[t] * 80 + aK[t] * 16) = pa[t];                    \
        _Pragma("unroll") for (int t = 0; t < 2; t++) {                                \
            int k = bK[t];                                                             \
            int x = bX[t] ^ (k & 7);                                                   \
            *(uint4*)((char*)Bs + k * 256 + x * 16) = pb[t];                           \
        }                                                                              \
    }

    LOADG(0);
    STOS();

    for (int kk = 0; kk < 48; kk++) {
        __syncthreads();
        if (kk < 47) LOADG(kk + 1);
#pragma unroll
        for (int ks = 0; ks < 2; ks++) {
            uint32_t a[2][4];
#pragma unroll
            for (int mi = 0; mi < 2; mi++) {
                int row = wm * 32 + mi * 16 + (lane & 15);
                ldsm4(a[mi], sA + row * 80 + (ks * 16 + (lane >> 4) * 8) * 2);
            }
            uint32_t bfr[4][4];
#pragma unroll
            for (int nb = 0; nb < 4; nb++) {
                int krow = ks * 16 + (lane & 7) + ((lane >> 3) & 1) * 8;
                int x = (wn * 8 + nb * 2 + (lane >> 4)) ^ (krow & 7);
                ldsm4t(bfr[nb], sB + krow * 256 + x * 16);
            }
#pragma unroll
            for (int mi = 0; mi < 2; mi++)
#pragma unroll
                for (int nj = 0; nj < 8; nj++)
                    mma16816(acc[mi][nj], a[mi], bfr[nj >> 1][(nj & 1) * 2],
                             bfr[nj >> 1][(nj & 1) * 2 + 1]);
        }
        __syncthreads();
        if (kk < 47) STOS();
    }
#undef LOADG
#undef STOS

#pragma unroll
    for (int mi = 0; mi < 2; mi++) {
        int r0 = o0 + wm * 32 + mi * 16 + (lane >> 2);
        float bi0 = bp[r0];
        float bi1 = bp[r0 + 8];
#pragma unroll
        for (int nj = 0; nj < 8; nj++) {
            int cb = l0 + wn * 64 + nj * 8 + (lane & 3) * 2;
            float2 v0 = make_float2(acc[mi][nj][0] + bi0, acc[mi][nj][1] + bi0);
            float2 v1 = make_float2(acc[mi][nj][2] + bi1, acc[mi][nj][3] + bi1);
            *(float2*)&C[(size_t)r0 * LL + cb] = v0;
            *(float2*)&C[(size_t)(r0 + 8) * LL + cb] = v1;
        }
    }
}

// ---------------------------------------------------------------------------
extern "C" void kernel_launch(void* const* d_in, const int* in_sizes, int n_in,
                              void* d_out, int out_size) {
    const float* x   = (const float*)d_in[0];
    const float* wq  = (const float*)d_in[1];
    const float* wk  = (const float*)d_in[2];
    const float* wv  = (const float*)d_in[3];
    const float* wp  = (const float*)d_in[4];
    const float* bp  = (const float*)d_in[5];
    const float* gq  = (const float*)d_in[6];
    const float* bq  = (const float*)d_in[7];
    const float* mq  = (const float*)d_in[8];
    const float* vq  = (const float*)d_in[9];
    const float* gk  = (const float*)d_in[10];
    const float* bk  = (const float*)d_in[11];
    const float* mk  = (const float*)d_in[12];
    const float* vk  = (const float*)d_in[13];
    const float* gv  = (const float*)d_in[14];
    const float* bv  = (const float*)d_in[15];
    const float* mv  = (const float*)d_in[16];
    const float* vv  = (const float*)d_in[17];
    const float* gp  = (const float*)d_in[18];
    const float* bpn = (const float*)d_in[19];
    const float* mp  = (const float*)d_in[20];
    const float* vp  = (const float*)d_in[21];
    float* out = (float*)d_out;

    k_split_w<<<(Cc * Cc + 255) / 256, 256>>>(wp);
    k_bn_lif_proj<<<(Bb * Cc * NN + 255) / 256, 256>>>(x, gp, bpn, mp, vp);
    k_gemm_qkv_f32<<<dim3(LL / 128, Cc / 128, 3 * Bb), 256>>>(wq, wk, wv);
    k_bn_lif_qkv<<<(3 * Bb * Cc * NN + 255) / 256, 256>>>(gq, bq, mq, vq,
                                                          gk, bk, mk, vk,
                                                          gv, bv, mv, vv);
    k_attn_mma<<<dim3(LL / 128, Bb * HH), 256>>>();
    k_gemm_out_mma<<<dim3(LL / 128, Cc / 128, Bb), 256>>>(bp, out);
}

// round 6
// speedup vs baseline: 1.8793x; 1.1079x over previous
#include <cuda_runtime.h>
#include <cuda_bf16.h>
#include <cstdint>

#define Bb 8
#define Cc 512
#define Tt 4
#define NN 256
#define LL 1024
#define HH 8
#define DD 64

typedef __nv_bfloat16 bf16;

// Scratch
__device__ bf16  g_wsp[3 * Cc * Cc];       // wp exact 3-way bf16 split
__device__ bf16  g_s0b[Bb * Cc * LL];      // proj spikes bf16 [b][c][l]
__device__ float g_y[3 * Bb * Cc * LL];    // qkv pre-activation fp32
__device__ bf16  g_qb[Bb * HH * LL * DD];  // q spikes [b][h][l][d]
__device__ bf16  g_kb[Bb * Cc * LL];       // k spikes [b][c][l] (= [b][h][d][l])
__device__ bf16  g_vb[Bb * HH * LL * DD];  // v spikes [b][h][l][d]
__device__ bf16  g_sattnb[Bb * Cc * LL];   // attn spikes [b][c][l]

// ---------------------------------------------------------------------------
__device__ __forceinline__ uint32_t smem_u32(const void* p) {
    return (uint32_t)__cvta_generic_to_shared(p);
}
__device__ __forceinline__ void ldsm4(uint32_t* r, uint32_t a) {
    asm volatile("ldmatrix.sync.aligned.m8n8.x4.shared.b16 {%0,%1,%2,%3}, [%4];"
                 : "=r"(r[0]), "=r"(r[1]), "=r"(r[2]), "=r"(r[3]) : "r"(a));
}
__device__ __forceinline__ void ldsm4t(uint32_t* r, uint32_t a) {
    asm volatile("ldmatrix.sync.aligned.m8n8.x4.trans.shared.b16 {%0,%1,%2,%3}, [%4];"
                 : "=r"(r[0]), "=r"(r[1]), "=r"(r[2]), "=r"(r[3]) : "r"(a));
}
__device__ __forceinline__ void mma16816(float* c, const uint32_t* a, uint32_t b0, uint32_t b1) {
    asm volatile(
        "mma.sync.aligned.m16n8k16.row.col.f32.bf16.bf16.f32 "
        "{%0,%1,%2,%3}, {%4,%5,%6,%7}, {%8,%9}, {%0,%1,%2,%3};"
        : "+f"(c[0]), "+f"(c[1]), "+f"(c[2]), "+f"(c[3])
        : "r"(a[0]), "r"(a[1]), "r"(a[2]), "r"(a[3]), "r"(b0), "r"(b1));
}
__device__ __forceinline__ uint32_t packbf(float lo, float hi) {
    uint32_t l = (uint32_t)__bfloat16_as_ushort(__float2bfloat16(lo));
    uint32_t h = (uint32_t)__bfloat16_as_ushort(__float2bfloat16(hi));
    return l | (h << 16);
}

// ---------------------------------------------------------------------------
// Kernel 0: exact 3-way bf16 split of wp only.
// ---------------------------------------------------------------------------
__global__ void k_split_w(const float* __restrict__ wp) {
    int idx = blockIdx.x * blockDim.x + threadIdx.x;
    if (idx >= Cc * Cc) return;
    float w = wp[idx];
    bf16 hi = __float2bfloat16(w);
    float r1 = w - __bfloat162float(hi);
    bf16 mid = __float2bfloat16(r1);
    float r2 = r1 - __bfloat162float(mid);
    g_wsp[0 * Cc * Cc + idx] = hi;
    g_wsp[1 * Cc * Cc + idx] = mid;
    g_wsp[2 * Cc * Cc + idx] = __float2bfloat16(r2);
}

// ---------------------------------------------------------------------------
// Kernel 1: proj BN + multi-step LIF -> g_s0b
// ---------------------------------------------------------------------------
__global__ void k_bn_lif_proj(const float* __restrict__ x,
                              const float* __restrict__ gp,
                              const float* __restrict__ bpn,
                              const float* __restrict__ mp,
                              const float* __restrict__ vp) {
    int idx = blockIdx.x * blockDim.x + threadIdx.x;
    if (idx >= Bb * Cc * NN) return;
    int n = idx % NN;
    int c = (idx / NN) % Cc;
    int b = idx / (NN * Cc);

    float sc = gp[c] / sqrtf(vp[c] + 1e-5f);
    float sh = bpn[c] - mp[c] * sc;

    const float* xp = x + ((size_t)(b * Cc + c) * Tt) * NN + n;
    bf16* sp = g_s0b + (size_t)(b * Cc + c) * LL + n;

    float v = 0.0f;
#pragma unroll
    for (int t = 0; t < Tt; t++) {
        float xb = xp[(size_t)t * NN] * sc + sh;
        v = v + (xb - v) / 1.5f;
        float s = (v >= 1.0f) ? 1.0f : 0.0f;
        sp[(size_t)t * NN] = __float2bfloat16(s);
        if (s != 0.0f) v = 0.0f;
    }
}

// ---------------------------------------------------------------------------
// Kernel 2: QKV projection, BITWISE fp32 FFMA (ascending k, single acc).
// 128x128 tile, BK=16, 256 threads, 8x8/thread, double-buffered smem.
// grid = (LL/128, Cc/128, 3*Bb)
// ---------------------------------------------------------------------------
__global__ __launch_bounds__(256, 2) void k_gemm_qkv_f32(const float* __restrict__ wq,
                                                         const float* __restrict__ wk,
                                                         const float* __restrict__ wv) {
    int z = blockIdx.z;
    int w = z >> 3, b = z & 7;
    const float* A = (w == 0) ? wq : (w == 1) ? wk : wv;
    const bf16* B = g_s0b + (size_t)b * Cc * LL;
    float* C = g_y + (size_t)z * Cc * LL;

    int o0 = blockIdx.y * 128, l0 = blockIdx.x * 128;
    int tid = threadIdx.x;
    int tx = tid & 15, ty = tid >> 4;

    __shared__ float As[2][16][128];
    __shared__ float Bs[2][16][128];

    int aRow = tid >> 1, aK = (tid & 1) * 8;
    int bRow = tid >> 4, bCh = tid & 15;

    float acc[8][8];
#pragma unroll
    for (int i = 0; i < 8; i++)
#pragma unroll
        for (int j = 0; j < 8; j++) acc[i][j] = 0.0f;

    float4 pa0, pa1;
    uint4 pbv;

#define PREF(k0)                                                              \
    {                                                                         \
        pa0 = *(const float4*)(A + (size_t)(o0 + aRow) * Cc + (k0) + aK);     \
        pa1 = *(const float4*)(A + (size_t)(o0 + aRow) * Cc + (k0) + aK + 4); \
        pbv = *(const uint4*)(B + (size_t)((k0) + bRow) * LL + l0 + bCh * 8); \
    }
#define STORE(buf)                                                              \
    {                                                                           \
        As[buf][aK + 0][aRow] = pa0.x; As[buf][aK + 1][aRow] = pa0.y;           \
        As[buf][aK + 2][aRow] = pa0.z; As[buf][aK + 3][aRow] = pa0.w;           \
        As[buf][aK + 4][aRow] = pa1.x; As[buf][aK + 5][aRow] = pa1.y;           \
        As[buf][aK + 6][aRow] = pa1.z; As[buf][aK + 7][aRow] = pa1.w;           \
        const __nv_bfloat162* pb2 = (const __nv_bfloat162*)&pbv;                \
        float4 f0, f1;                                                          \
        { float2 t0 = __bfloat1622float2(pb2[0]); f0.x = t0.x; f0.y = t0.y; }   \
        { float2 t1 = __bfloat1622float2(pb2[1]); f0.z = t1.x; f0.w = t1.y; }   \
        { float2 t2 = __bfloat1622float2(pb2[2]); f1.x = t2.x; f1.y = t2.y; }   \
        { float2 t3 = __bfloat1622float2(pb2[3]); f1.z = t3.x; f1.w = t3.y; }   \
        *(float4*)&Bs[buf][bRow][bCh * 8] = f0;                                 \
        *(float4*)&Bs[buf][bRow][bCh * 8 + 4] = f1;                             \
    }

    PREF(0);
    STORE(0);
    __syncthreads();

    for (int kt = 0; kt < 32; kt++) {
        int cur = kt & 1;
        if (kt < 31) PREF((kt + 1) * 16);
#pragma unroll
        for (int kk = 0; kk < 16; kk++) {
            float a[8], bv[8];
            *(float4*)&a[0]  = *(const float4*)&As[cur][kk][ty * 8];
            *(float4*)&a[4]  = *(const float4*)&As[cur][kk][ty * 8 + 4];
            *(float4*)&bv[0] = *(const float4*)&Bs[cur][kk][tx * 8];
            *(float4*)&bv[4] = *(const float4*)&Bs[cur][kk][tx * 8 + 4];
#pragma unroll
            for (int i = 0; i < 8; i++)
#pragma unroll
                for (int j = 0; j < 8; j++) acc[i][j] += a[i] * bv[j];
        }
        if (kt < 31) { STORE(!cur); }
        __syncthreads();
    }
#undef PREF
#undef STORE

#pragma unroll
    for (int i = 0; i < 8; i++) {
        int o = o0 + ty * 8 + i;
        *(float4*)&C[(size_t)o * LL + l0 + tx * 8]     = *(float4*)&acc[i][0];
        *(float4*)&C[(size_t)o * LL + l0 + tx * 8 + 4] = *(float4*)&acc[i][4];
    }
}

// ---------------------------------------------------------------------------
// Kernel 3 (REWORKED): per-branch BN + LIF with coalesced I/O.
// grid = (NN/32, HH, 3*Bb), block 256 (8 warps).
// Warp reads 32 consecutive n for one channel o (coalesced); LIF bit-identical;
// q/v spikes staged in padded smem then written as contiguous [l][d] rows;
// k spikes stored directly (layout already coalesced).
// ---------------------------------------------------------------------------
__global__ __launch_bounds__(256) void k_bn_lif_qkv(
        const float* __restrict__ gq, const float* __restrict__ bq,
        const float* __restrict__ mq, const float* __restrict__ vq,
        const float* __restrict__ gk, const float* __restrict__ bk,
        const float* __restrict__ mk, const float* __restrict__ vk,
        const float* __restrict__ gv, const float* __restrict__ bv,
        const float* __restrict__ mv, const float* __restrict__ vv) {
    int z = blockIdx.z;
    int w = z / Bb, b = z % Bb;
    int h = blockIdx.y;
    int n0 = blockIdx.x * 32;
    int tid = threadIdx.x, lane = tid & 31, wrp = tid >> 5;

    const float *gg, *bb, *mm, *vvv;
    if (w == 0) { gg = gq; bb = bq; mm = mq; vvv = vq; }
    else if (w == 1) { gg = gk; bb = bk; mm = mk; vvv = vk; }
    else { gg = gv; bb = bv; mm = mv; vvv = vv; }

    const bool isK = (w == 1);
    __shared__ bf16 sm[Tt][32][66];   // [t][n][dd] padded (33 u32 stride: conflict-free)

#pragma unroll
    for (int i = 0; i < 8; i++) {
        int od = wrp * 8 + i;         // dd in [0,64)
        int o = h * 64 + od;
        float sc = gg[o] / sqrtf(vvv[o] + 1e-5f);
        float sh = bb[o] - mm[o] * sc;
        const float* yp = g_y + (size_t)((w * Bb + b) * Cc + o) * LL + n0 + lane;

        float v = 0.0f;
#pragma unroll
        for (int t = 0; t < Tt; t++) {
            float yb = yp[(size_t)t * NN] * sc + sh;
            v = v + (yb - v) / 1.5f;
            float s = (v >= 1.0f) ? 1.0f : 0.0f;
            if (isK)
                g_kb[(size_t)(b * Cc + o) * LL + t * NN + n0 + lane] = __float2bfloat16(s);
            else
                sm[t][lane][od] = __float2bfloat16(s);
            if (s != 0.0f) v = 0.0f;
        }
    }

    if (!isK) {
        __syncthreads();
        bf16* dst = ((w == 0) ? g_qb : g_vb) + (size_t)(b * HH + h) * LL * DD;
        // 128 rows (4t x 32n) x 32 u32 each; one warp per row chunk -> 128B stores
#pragma unroll
        for (int j = 0; j < 16; j++) {
            int flat = tid + 256 * j;      // 0..4095
            int row = flat >> 5, col = flat & 31;
            int t = row >> 5, n = row & 31;
            uint32_t val;
            memcpy(&val, &sm[t][n][col * 2], 4);
            *(uint32_t*)(dst + ((size_t)(t * NN + n0 + n)) * DD + col * 2) = val;
        }
    }
}

// ---------------------------------------------------------------------------
// Kernel 4: attention on tensor cores (exact: binary inputs, integer sums).
// ---------------------------------------------------------------------------
__global__ __launch_bounds__(256) void k_attn_mma() {
    int l0 = blockIdx.x * 128;
    int bh = blockIdx.y;
    int b = bh >> 3, h = bh & 7;

    const bf16* Q = g_qb + (size_t)bh * LL * DD;              // [l][d]
    const bf16* K = g_kb + (size_t)(b * Cc + h * 64) * LL;    // [d][l]
    const bf16* V = g_vb + (size_t)bh * LL * DD;              // [l][d]

    __shared__ bf16 Qs[128 * 72];
    __shared__ bf16 Ks[64 * 64];
    __shared__ bf16 Vs[64 * 64];

    int tid = threadIdx.x, lane = tid & 31, warp = tid >> 5;
    const uint32_t sQ = smem_u32(Qs), sK = smem_u32(Ks), sV = smem_u32(Vs);

#pragma unroll
    for (int t = 0; t < 4; t++) {
        int id = tid + t * 256;
        int r = id >> 3, c = id & 7;
        uint4 qv = *(const uint4*)(Q + (size_t)(l0 + r) * DD + c * 8);
        *(uint4*)((char*)Qs + r * 144 + c * 16) = qv;
    }
    __syncthreads();

    uint32_t aq[4][4];
    {
        int row = warp * 16 + (lane & 15);
#pragma unroll
        for (int kc = 0; kc < 4; kc++)
            ldsm4(aq[kc], sQ + row * 144 + kc * 32 + (lane >> 4) * 16);
    }

    float oacc[8][4];
#pragma unroll
    for (int i = 0; i < 8; i++)
#pragma unroll
        for (int j = 0; j < 4; j++) oacc[i][j] = 0.0f;

    for (int k0 = 0; k0 < LL; k0 += 64) {
        __syncthreads();
#pragma unroll
        for (int t = 0; t < 2; t++) {
            int id = tid + t * 256;
            int r = id >> 3, c = id & 7;
            int x = c ^ (r & 7);
            uint4 kv = *(const uint4*)(K + (size_t)r * LL + k0 + c * 8);
            *(uint4*)((char*)Ks + r * 128 + x * 16) = kv;
            uint4 vv = *(const uint4*)(V + (size_t)(k0 + r) * DD + c * 8);
            *(uint4*)((char*)Vs + r * 128 + x * 16) = vv;
        }
        __syncthreads();

        float sacc[8][4];
#pragma unroll
        for (int i = 0; i < 8; i++)
#pragma unroll
            for (int j = 0; j < 4; j++) sacc[i][j] = 0.0f;
#pragma unroll
        for (int nb = 0; nb < 4; nb++) {
#pragma unroll
            for (int ks = 0; ks < 4; ks++) {
                uint32_t bf[4];
                int krow = ks * 16 + (lane & 7) + ((lane >> 3) & 1) * 8;
                int ch = nb * 2 + (lane >> 4);
                int x = ch ^ (krow & 7);
                ldsm4t(bf, sK + krow * 128 + x * 16);
                mma16816(sacc[nb * 2],     aq[ks], bf[0], bf[1]);
                mma16816(sacc[nb * 2 + 1], aq[ks], bf[2], bf[3]);
            }
        }
        uint32_t sa[4][4];
#pragma unroll
        for (int kb = 0; kb < 4; kb++) {
            sa[kb][0] = packbf(sacc[2 * kb][0],     sacc[2 * kb][1]);
            sa[kb][1] = packbf(sacc[2 * kb][2],     sacc[2 * kb][3]);
            sa[kb][2] = packbf(sacc[2 * kb + 1][0], sacc[2 * kb + 1][1]);
            sa[kb][3] = packbf(sacc[2 * kb + 1][2], sacc[2 * kb + 1][3]);
        }
#pragma unroll
        for (int nb = 0; nb < 4; nb++) {
#pragma unroll
            for (int kb = 0; kb < 4; kb++) {
                uint32_t bf[4];
                int krow = kb * 16 + (lane & 7) + ((lane >> 3) & 1) * 8;
                int ch = nb * 2 + (lane >> 4);
                int x = ch ^ (krow & 7);
                ldsm4t(bf, sV + krow * 128 + x * 16);
                mma16816(oacc[nb * 2],     sa[kb], bf[0], bf[1]);
                mma16816(oacc[nb * 2 + 1], sa[kb], bf[2], bf[3]);
            }
        }
    }

    int row = warp * 16 + (lane >> 2);
#pragma unroll
    for (int nj = 0; nj < 8; nj++) {
        int col = nj * 8 + (lane & 3) * 2;
#pragma unroll
        for (int e = 0; e < 4; e++) {
            int r = row + (e >> 1) * 8;
            int c = col + (e & 1);
            float o = oacc[nj][e] * 0.125f;
            float s = ((o / 1.5f - 1.0f) >= 0.0f) ? 1.0f : 0.0f;
            g_sattnb[((size_t)b * Cc + h * 64 + c) * LL + (l0 + r)] = __float2bfloat16(s);
        }
    }
}

// ---------------------------------------------------------------------------
// Kernel 5: output projection via 3-split bf16 MMA (after last threshold).
// ---------------------------------------------------------------------------
__global__ __launch_bounds__(256, 2) void k_gemm_out_mma(const float* __restrict__ bp,
                                                         float* __restrict__ out) {
    const bf16* A = g_wsp;
    const bf16* B = g_sattnb + (size_t)blockIdx.z * Cc * LL;
    float* C = out + (size_t)blockIdx.z * Cc * LL;

    __shared__ bf16 As[128 * 40];
    __shared__ bf16 Bs[32 * 128];

    const int tid = threadIdx.x;
    const int lane = tid & 31, warp = tid >> 5;
    const int wm = warp >> 1, wn = warp & 1;
    const int o0 = blockIdx.y * 128, l0 = blockIdx.x * 128;

    float acc[2][8][4];
#pragma unroll
    for (int i = 0; i < 2; i++)
#pragma unroll
        for (int j = 0; j < 8; j++)
#pragma unroll
            for (int k = 0; k < 4; k++) acc[i][j][k] = 0.0f;

    int aM[2], aK[2], bK[2], bX[2];
#pragma unroll
    for (int t = 0; t < 2; t++) {
        int id = tid + t * 256;
        aM[t] = id >> 2; aK[t] = id & 3;
        bK[t] = id >> 4; bX[t] = id & 15;
    }
    uint4 pa[2], pb[2];
    const uint32_t sA = smem_u32(As), sB = smem_u32(Bs);

#define LOADG(kk)                                                                      \
    {                                                                                  \
        int split = ((kk) * 32) >> 9;                                                  \
        int c0 = ((kk) * 32) & 511;                                                    \
        const bf16* Ab = A + (size_t)split * (Cc * Cc);                                \
        _Pragma("unroll") for (int t = 0; t < 2; t++)                                  \
            pa[t] = *(const uint4*)(Ab + (size_t)(o0 + aM[t]) * Cc + c0 + aK[t] * 8);  \
        _Pragma("unroll") for (int t = 0; t < 2; t++)                                  \
            pb[t] = *(const uint4*)(B + (size_t)(c0 + bK[t]) * LL + l0 + bX[t] * 8);   \
    }
#define STOS()                                                                         \
    {                                                                                  \
        _Pragma("unroll") for (int t = 0; t < 2; t++)                                  \
            *(uint4*)((char*)As + aM[t] * 80 + aK[t] * 16) = pa[t];                    \
        _Pragma("unroll") for (int t = 0; t < 2; t++) {                                \
            int k = bK[t];                                                             \
            int x = bX[t] ^ (k & 7);                                                   \
            *(uint4*)((char*)Bs + k * 256 + x * 16) = pb[t];                           \
        }                                                                              \
    }

    LOADG(0);
    STOS();

    for (int kk = 0; kk < 48; kk++) {
        __syncthreads();
        if (kk < 47) LOADG(kk + 1);
#pragma unroll
        for (int ks = 0; ks < 2; ks++) {
            uint32_t a[2][4];
#pragma unroll
            for (int mi = 0; mi < 2; mi++) {
                int row = wm * 32 + mi * 16 + (lane & 15);
                ldsm4(a[mi], sA + row * 80 + (ks * 16 + (lane >> 4) * 8) * 2);
            }
            uint32_t bfr[4][4];
#pragma unroll
            for (int nb = 0; nb < 4; nb++) {
                int krow = ks * 16 + (lane & 7) + ((lane >> 3) & 1) * 8;
                int x = (wn * 8 + nb * 2 + (lane >> 4)) ^ (krow & 7);
                ldsm4t(bfr[nb], sB + krow * 256 + x * 16);
            }
#pragma unroll
            for (int mi = 0; mi < 2; mi++)
#pragma unroll
                for (int nj = 0; nj < 8; nj++)
                    mma16816(acc[mi][nj], a[mi], bfr[nj >> 1][(nj & 1) * 2],
                             bfr[nj >> 1][(nj & 1) * 2 + 1]);
        }
        __syncthreads();
        if (kk < 47) STOS();
    }
#undef LOADG
#undef STOS

#pragma unroll
    for (int mi = 0; mi < 2; mi++) {
        int r0 = o0 + wm * 32 + mi * 16 + (lane >> 2);
        float bi0 = bp[r0];
        float bi1 = bp[r0 + 8];
#pragma unroll
        for (int nj = 0; nj < 8; nj++) {
            int cb = l0 + wn * 64 + nj * 8 + (lane & 3) * 2;
            float2 v0 = make_float2(acc[mi][nj][0] + bi0, acc[mi][nj][1] + bi0);
            float2 v1 = make_float2(acc[mi][nj][2] + bi1, acc[mi][nj][3] + bi1);
            *(float2*)&C[(size_t)r0 * LL + cb] = v0;
            *(float2*)&C[(size_t)(r0 + 8) * LL + cb] = v1;
        }
    }
}

// ---------------------------------------------------------------------------
extern "C" void kernel_launch(void* const* d_in, const int* in_sizes, int n_in,
                              void* d_out, int out_size) {
    const float* x   = (const float*)d_in[0];
    const float* wq  = (const float*)d_in[1];
    const float* wk  = (const float*)d_in[2];
    const float* wv  = (const float*)d_in[3];
    const float* wp  = (const float*)d_in[4];
    const float* bp  = (const float*)d_in[5];
    const float* gq  = (const float*)d_in[6];
    const float* bq  = (const float*)d_in[7];
    const float* mq  = (const float*)d_in[8];
    const float* vq  = (const float*)d_in[9];
    const float* gk  = (const float*)d_in[10];
    const float* bk  = (const float*)d_in[11];
    const float* mk  = (const float*)d_in[12];
    const float* vk  = (const float*)d_in[13];
    const float* gv  = (const float*)d_in[14];
    const float* bv  = (const float*)d_in[15];
    const float* mv  = (const float*)d_in[16];
    const float* vv  = (const float*)d_in[17];
    const float* gp  = (const float*)d_in[18];
    const float* bpn = (const float*)d_in[19];
    const float* mp  = (const float*)d_in[20];
    const float* vp  = (const float*)d_in[21];
    float* out = (float*)d_out;

    k_split_w<<<(Cc * Cc + 255) / 256, 256>>>(wp);
    k_bn_lif_proj<<<(Bb * Cc * NN + 255) / 256, 256>>>(x, gp, bpn, mp, vp);
    k_gemm_qkv_f32<<<dim3(LL / 128, Cc / 128, 3 * Bb), 256>>>(wq, wk, wv);
    k_bn_lif_qkv<<<dim3(NN / 32, HH, 3 * Bb), 256>>>(gq, bq, mq, vq,
                                                     gk, bk, mk, vk,
                                                     gv, bv, mv, vv);
    k_attn_mma<<<dim3(LL / 128, Bb * HH), 256>>>();
    k_gemm_out_mma<<<dim3(LL / 128, Cc / 128, Bb), 256>>>(bp, out);
}